// round 1
// baseline (speedup 1.0000x reference)
#include <cuda_runtime.h>
#include <cuda_bf16.h>
#include <cstdint>

// ---------------------------------------------------------------------------
// GCN layer: out = segment_sum((X @ W)[src] * val, dst) + bias
// N_NODES=100000, E=3200000, IN=OUT=128
// ---------------------------------------------------------------------------

#define IN_DIM  128
#define OUT_DIM 128
#define MAX_NODES 100000

// Scratch for H = X @ W  (51.2 MB). Device global: allocation-free.
__device__ float g_H[(size_t)MAX_NODES * OUT_DIM];

// ---------------------------------------------------------------------------
// Kernel 1: H = X @ W   (tiled SGEMM, BM=128, BN=128, BK=32, 8x8 reg tile)
// ---------------------------------------------------------------------------
#define BM 128
#define BN 128
#define BK 32

__global__ void __launch_bounds__(256, 2)
gemm_kernel(const float* __restrict__ X, const float* __restrict__ W,
            float* __restrict__ H, int N)
{
    __shared__ float sA[BK][BM + 4];   // A transposed: sA[k][m]
    __shared__ float sB[BK][BN];       // W chunk:      sB[k][n]

    const int tid = threadIdx.x;
    const int tx  = tid & 15;          // 16 col-groups of 8
    const int ty  = tid >> 4;          // 16 row-groups of 8
    const int rowBase = blockIdx.x * BM;

    float acc[8][8];
#pragma unroll
    for (int i = 0; i < 8; i++)
#pragma unroll
        for (int j = 0; j < 8; j++) acc[i][j] = 0.f;

    for (int k0 = 0; k0 < IN_DIM; k0 += BK) {
        // Load A tile: 128 rows x 32 k  (1024 float4, 4 per thread), transpose into sA
#pragma unroll
        for (int i = 0; i < 4; i++) {
            int idx = tid + i * 256;         // 0..1023
            int m   = idx >> 3;              // 0..127
            int kk  = (idx & 7) << 2;        // 0,4,...,28
            int row = rowBase + m;
            float4 v = make_float4(0.f, 0.f, 0.f, 0.f);
            if (row < N)
                v = *(const float4*)&X[(size_t)row * IN_DIM + k0 + kk];
            sA[kk + 0][m] = v.x;
            sA[kk + 1][m] = v.y;
            sA[kk + 2][m] = v.z;
            sA[kk + 3][m] = v.w;
        }
        // Load B tile: 32 k x 128 n (1024 float4, 4 per thread)
#pragma unroll
        for (int i = 0; i < 4; i++) {
            int idx = tid + i * 256;
            int kk  = idx >> 5;              // 0..31
            int n   = (idx & 31) << 2;       // 0,4,...,124
            *(float4*)&sB[kk][n] = *(const float4*)&W[(size_t)(k0 + kk) * OUT_DIM + n];
        }
        __syncthreads();

#pragma unroll
        for (int kk = 0; kk < BK; kk++) {
            float a[8], b[8];
            float4 a0 = *(const float4*)&sA[kk][ty * 8];
            float4 a1 = *(const float4*)&sA[kk][ty * 8 + 4];
            float4 b0 = *(const float4*)&sB[kk][tx * 8];
            float4 b1 = *(const float4*)&sB[kk][tx * 8 + 4];
            a[0]=a0.x; a[1]=a0.y; a[2]=a0.z; a[3]=a0.w;
            a[4]=a1.x; a[5]=a1.y; a[6]=a1.z; a[7]=a1.w;
            b[0]=b0.x; b[1]=b0.y; b[2]=b0.z; b[3]=b0.w;
            b[4]=b1.x; b[5]=b1.y; b[6]=b1.z; b[7]=b1.w;
#pragma unroll
            for (int i = 0; i < 8; i++)
#pragma unroll
                for (int j = 0; j < 8; j++)
                    acc[i][j] += a[i] * b[j];
        }
        __syncthreads();
    }

    // Store 8x8 tile
#pragma unroll
    for (int i = 0; i < 8; i++) {
        int row = rowBase + ty * 8 + i;
        if (row < N) {
            float* p = &H[(size_t)row * OUT_DIM + tx * 8];
            *(float4*)p       = make_float4(acc[i][0], acc[i][1], acc[i][2], acc[i][3]);
            *(float4*)(p + 4) = make_float4(acc[i][4], acc[i][5], acc[i][6], acc[i][7]);
        }
    }
}

// ---------------------------------------------------------------------------
// Kernel 2: out[i] = bias[i % 128]
// ---------------------------------------------------------------------------
__global__ void __launch_bounds__(256)
init_out_kernel(float* __restrict__ out, const float* __restrict__ bias, int total4)
{
    int i = blockIdx.x * blockDim.x + threadIdx.x;   // index in float4 units
    if (i < total4) {
        int c = (i & 31) << 2;                       // column of this float4 (128 cols = 32 float4)
        float4 b = *(const float4*)&bias[c];
        ((float4*)out)[i] = b;
    }
}

// ---------------------------------------------------------------------------
// Kernel 3: SpMM aggregation — one warp per edge, vectorized L2 atomics.
//   out[dst] += val * H[src]
// ---------------------------------------------------------------------------
__global__ void __launch_bounds__(256)
spmm_kernel(const float* __restrict__ H,
            const int* __restrict__ src, const int* __restrict__ dst,
            const float* __restrict__ val,
            float* __restrict__ out, int E)
{
    const int lane   = threadIdx.x & 31;
    const int warp   = (blockIdx.x * blockDim.x + threadIdx.x) >> 5;
    const int nwarps = (gridDim.x * blockDim.x) >> 5;

    for (int e = warp; e < E; e += nwarps) {
        const int   s = __ldg(&src[e]);
        const int   d = __ldg(&dst[e]);
        const float v = __ldg(&val[e]);

        const float4 h4 = *(const float4*)&H[(size_t)s * OUT_DIM + lane * 4];
        float* p = &out[(size_t)d * OUT_DIM + lane * 4];
        asm volatile("red.global.add.v4.f32 [%0], {%1, %2, %3, %4};"
                     :: "l"(p),
                        "f"(h4.x * v), "f"(h4.y * v), "f"(h4.z * v), "f"(h4.w * v)
                     : "memory");
    }
}

// ---------------------------------------------------------------------------
// Launch
// ---------------------------------------------------------------------------
extern "C" void kernel_launch(void* const* d_in, const int* in_sizes, int n_in,
                              void* d_out, int out_size)
{
    const float* features  = (const float*)d_in[0];
    const int*   edge_src  = (const int*)  d_in[1];
    const int*   edge_dst  = (const int*)  d_in[2];
    const float* edge_vals = (const float*)d_in[3];
    const float* weight    = (const float*)d_in[4];
    const float* bias      = (const float*)d_in[5];
    float*       out       = (float*)d_out;

    const int N = in_sizes[0] / IN_DIM;     // 100000
    const int E = in_sizes[1];              // 3200000

    float* H;
    cudaGetSymbolAddress((void**)&H, g_H);

    // 1) H = X @ W
    int gemm_blocks = (N + BM - 1) / BM;
    gemm_kernel<<<gemm_blocks, 256>>>(features, weight, H, N);

    // 2) out = broadcast(bias)
    int total4 = out_size / 4;
    init_out_kernel<<<(total4 + 255) / 256, 256>>>(out, bias, total4);

    // 3) out[dst] += val * H[src]
    int spmm_blocks = 148 * 16;             // 2368 blocks -> 18944 warps, grid-stride
    spmm_kernel<<<spmm_blocks, 256>>>(H, edge_src, edge_dst, edge_vals, out, E);
}